// round 1
// baseline (speedup 1.0000x reference)
#include <cuda_runtime.h>
#include <math.h>

// Problem constants
#define B_    8
#define LP    256
#define TM_   1024
#define TG_   256
#define MELC  80
#define H_    512
#define NH_   8
#define DH_   64
#define LC_   512
#define TOUT  1536
#define KG_   31

// ---------------- device scratch (no cudaMalloc allowed) ----------------
__device__ float d_melX[8192 * 240];             // im2col for mel conv (K=240)
__device__ float d_mel [8192 * 512];             // mel features [b*t][c]
__device__ float d_q   [2048 * 512];
__device__ float d_kv  [8192 * 1024];            // [bt][ k(512) | v(512) ]
__device__ float d_S   [64 * 256 * 1024];        // scores / attn per (b,h)
__device__ float d_ctx [2048 * 512];
__device__ float d_attn[2048 * 512];
__device__ float d_ga  [2048 * 512];             // g ping
__device__ float d_gb  [2048 * 512];             // g pong
__device__ float d_gX  [2048 * 15872];           // im2col for g layers (130MB)
__device__ int   d_rowsrc[B_ * TOUT];

// ---------------- generic fp32 GEMM ----------------
// C[M,N] = alpha * A[M,K] @ op(B) + bias, optional relu.
// TRANSB=true : B is [N,K] row-major (weights), C = A*B^T
// TRANSB=false: B is [K,N] row-major,            C = A*B
// Batched via blockIdx.z with split strides: off = (z/zdiv)*s1 + (z%zdiv)*s2
// Requires M%128==0, N%64==0, K%16==0, all leading dims %4==0.
template<bool TRANSB, bool RELU>
__global__ void __launch_bounds__(256, 2)
gemm_kernel(int M, int N, int K,
            const float* __restrict__ A, int lda, long long sA1, long long sA2,
            const float* __restrict__ Bp, int ldb, long long sB1, long long sB2,
            float* __restrict__ C, int ldc, long long sC1, long long sC2,
            const float* __restrict__ bias, float alpha, int zdiv)
{
    __shared__ float As[16][132];
    __shared__ float Bs[16][68];

    int z  = blockIdx.z;
    int z1 = z / zdiv, z2 = z - z1 * zdiv;
    A  += (long long)z1 * sA1 + (long long)z2 * sA2;
    Bp += (long long)z1 * sB1 + (long long)z2 * sB2;
    C  += (long long)z1 * sC1 + (long long)z2 * sC2;

    int tid  = threadIdx.x;
    int row0 = blockIdx.y * 128;
    int col0 = blockIdx.x * 64;

    int am  = tid >> 2;            // 0..63
    int ak  = (tid & 3) << 2;      // 0,4,8,12
    int bn  = tid >> 2;
    int bk  = (tid & 3) << 2;
    int bks = tid >> 4;            // 0..15
    int bn4 = (tid & 15) << 2;     // 0..60

    const float* Arow0 = A + (long long)(row0 + am) * lda + ak;
    const float* Arow1 = Arow0 + (long long)64 * lda;
    const float* Brow  = TRANSB ? (Bp + (long long)(col0 + bn) * ldb + bk)
                                : (Bp + (long long)bks * ldb + col0 + bn4);

    float4 pa0 = *(const float4*)(Arow0);
    float4 pa1 = *(const float4*)(Arow1);
    float4 pb  = *(const float4*)(Brow);

    float acc[8][4];
    #pragma unroll
    for (int i = 0; i < 8; i++)
        #pragma unroll
        for (int j = 0; j < 4; j++) acc[i][j] = 0.f;

    int tm = (tid >> 4) << 3;      // 0..120 step 8
    int tn = (tid & 15) << 2;      // 0..60  step 4

    for (int k0 = 0; k0 < K; k0 += 16) {
        As[ak+0][am]    = pa0.x; As[ak+1][am]    = pa0.y; As[ak+2][am]    = pa0.z; As[ak+3][am]    = pa0.w;
        As[ak+0][am+64] = pa1.x; As[ak+1][am+64] = pa1.y; As[ak+2][am+64] = pa1.z; As[ak+3][am+64] = pa1.w;
        if (TRANSB) { Bs[bk+0][bn] = pb.x; Bs[bk+1][bn] = pb.y; Bs[bk+2][bn] = pb.z; Bs[bk+3][bn] = pb.w; }
        else        { *(float4*)&Bs[bks][bn4] = pb; }
        __syncthreads();

        int kn = k0 + 16;
        if (kn < K) {   // prefetch next tile into regs while computing
            pa0 = *(const float4*)(Arow0 + kn);
            pa1 = *(const float4*)(Arow1 + kn);
            pb  = TRANSB ? *(const float4*)(Brow + kn)
                         : *(const float4*)(Brow + (long long)kn * ldb);
        }

        #pragma unroll
        for (int kk = 0; kk < 16; kk++) {
            float a[8], bb[4];
            *(float4*)&a[0]  = *(const float4*)&As[kk][tm];
            *(float4*)&a[4]  = *(const float4*)&As[kk][tm + 4];
            *(float4*)&bb[0] = *(const float4*)&Bs[kk][tn];
            #pragma unroll
            for (int i = 0; i < 8; i++)
                #pragma unroll
                for (int j = 0; j < 4; j++)
                    acc[i][j] = fmaf(a[i], bb[j], acc[i][j]);
        }
        __syncthreads();
    }

    float4 bv = make_float4(0.f, 0.f, 0.f, 0.f);
    if (bias) bv = *(const float4*)(bias + col0 + tn);
    #pragma unroll
    for (int i = 0; i < 8; i++) {
        float4 o;
        o.x = fmaf(acc[i][0], alpha, bv.x);
        o.y = fmaf(acc[i][1], alpha, bv.y);
        o.z = fmaf(acc[i][2], alpha, bv.z);
        o.w = fmaf(acc[i][3], alpha, bv.w);
        if (RELU) { o.x = fmaxf(o.x, 0.f); o.y = fmaxf(o.y, 0.f); o.z = fmaxf(o.z, 0.f); o.w = fmaxf(o.w, 0.f); }
        *(float4*)(C + (long long)(row0 + tm + i) * ldc + col0 + tn) = o;
    }
}

// ---------------- im2col kernels ----------------
// mel conv: X[bt][m*3+kk] = mel_spec[b][m][t+kk-1], bt over B*TM
__global__ void im2col_mel(const float* __restrict__ x, float* __restrict__ X)
{
    int idx = blockIdx.x * 256 + threadIdx.x;
    if (idx >= 8192 * 80) return;
    int m  = idx % 80;
    int bt = idx / 80;
    int b  = bt >> 10;
    int t  = bt & 1023;
    const float* src = x + (long long)(b * 80 + m) * 1024;
    float* dst = X + (long long)bt * 240 + m * 3;
    #pragma unroll
    for (int kk = 0; kk < 3; kk++) {
        int tt = t + kk - 1;
        dst[kk] = (tt >= 0 && tt < 1024) ? src[tt] : 0.f;
    }
}

// g0 conv: X[bt][m*31+kk] = gms[b][m][t+kk-15], bt over B*TG
__global__ void im2col_g0(const float* __restrict__ x, float* __restrict__ X)
{
    int idx = blockIdx.x * 256 + threadIdx.x;
    if (idx >= 2048 * 80) return;
    int m  = idx % 80;
    int bt = idx / 80;
    int b  = bt >> 8;
    int t  = bt & 255;
    const float* src = x + (long long)(b * 80 + m) * 256;
    float* dst = X + (long long)bt * 2480 + m * 31;
    #pragma unroll
    for (int kk = 0; kk < 31; kk++) {
        int tt = t + kk - 15;
        dst[kk] = (tt >= 0 && tt < 256) ? src[tt] : 0.f;
    }
}

// g layers: X[bt][ci*31+kk] = g[b][t+kk-15][ci]  (g is [b*t][c] row-major)
__global__ void im2col_g(const float* __restrict__ g, float* __restrict__ X)
{
    int idx = blockIdx.x * 256 + threadIdx.x;   // (bt, ci)
    int ci = idx & 511;
    int bt = idx >> 9;
    int b  = bt >> 8;
    int t  = bt & 255;
    const float* src = g + (long long)(b * 256) * 512 + ci;
    float* dst = X + (long long)bt * 15872 + ci * 31;
    #pragma unroll
    for (int kk = 0; kk < 31; kk++) {
        int tt = t + kk - 15;
        dst[kk] = (tt >= 0 && tt < 256) ? src[(long long)tt * 512] : 0.f;
    }
}

// ---------------- softmax over rows of length 1024 ----------------
__global__ void softmax1024(float* __restrict__ S)
{
    float4* row = (float4*)(S + (long long)blockIdx.x * 1024);
    int tid = threadIdx.x;                    // 256 threads, 4 cols each
    float4 v = row[tid];
    float m = fmaxf(fmaxf(v.x, v.y), fmaxf(v.z, v.w));
    __shared__ float red[8];
    #pragma unroll
    for (int o = 16; o; o >>= 1) m = fmaxf(m, __shfl_xor_sync(0xffffffffu, m, o));
    if ((tid & 31) == 0) red[tid >> 5] = m;
    __syncthreads();
    float bm = red[0];
    #pragma unroll
    for (int i = 1; i < 8; i++) bm = fmaxf(bm, red[i]);

    v.x = expf(v.x - bm); v.y = expf(v.y - bm);
    v.z = expf(v.z - bm); v.w = expf(v.w - bm);
    float s = v.x + v.y + v.z + v.w;
    #pragma unroll
    for (int o = 16; o; o >>= 1) s += __shfl_xor_sync(0xffffffffu, s, o);
    __syncthreads();
    if ((tid & 31) == 0) red[tid >> 5] = s;
    __syncthreads();
    float bs = 0.f;
    #pragma unroll
    for (int i = 0; i < 8; i++) bs += red[i];
    float inv = 1.f / bs;
    v.x *= inv; v.y *= inv; v.z *= inv; v.w *= inv;
    row[tid] = v;
}

// ---------------- length-regulator scatter ----------------
__global__ void build_map(const int* __restrict__ tl, int* __restrict__ rowsrc)
{
    int b = blockIdx.x;
    __shared__ int cum[LC_];
    int l = threadIdx.x;                      // 512 threads
    cum[l] = tl[b * LC_ + l];
    __syncthreads();
    if (l == 0) {
        int s = 0;
        for (int i = 0; i < LC_; i++) { s += cum[i]; cum[i] = s; }
    }
    __syncthreads();
    for (int t = l; t < TOUT; t += LC_) rowsrc[b * TOUT + t] = -1;
    __syncthreads();
    int e = cum[l];
    int s = e - tl[b * LC_ + l];
    for (int t = s; t < e; t++) rowsrc[b * TOUT + t] = l;
}

__global__ void gather_out(const int* __restrict__ rowsrc,
                           const float* __restrict__ attn,
                           const float* __restrict__ g,
                           float* __restrict__ out)
{
    int bt = blockIdx.x;                      // B*TOUT blocks
    int b  = bt / TOUT;
    int l  = rowsrc[bt];
    float4 v = make_float4(0.f, 0.f, 0.f, 0.f);
    if (l >= 0) {
        const float* src = (l < LP) ? attn + (long long)(b * LP + l) * H_
                                    : g    + (long long)(b * TG_ + (l - LP)) * H_;
        v = ((const float4*)src)[threadIdx.x];   // 128 threads * float4 = 512
    }
    ((float4*)(out + (long long)bt * H_))[threadIdx.x] = v;
}

// ---------------- launch ----------------
extern "C" void kernel_launch(void* const* d_in, const int* in_sizes, int n_in,
                              void* d_out, int out_size)
{
    const float* phone    = (const float*)d_in[0];
    const float* mel_spec = (const float*)d_in[1];
    const float* gms      = (const float*)d_in[2];
    const int*   tl       = (const int*)  d_in[3];
    const float* mel_w    = (const float*)d_in[4];
    const float* mel_b    = (const float*)d_in[5];
    const float* inw      = (const float*)d_in[6];
    const float* inb      = (const float*)d_in[7];
    const float* ow       = (const float*)d_in[8];
    const float* ob       = (const float*)d_in[9];
    const float* g0w      = (const float*)d_in[10];
    const float* g0b      = (const float*)d_in[11];
    const float* gws      = (const float*)d_in[12];
    const float* gbs      = (const float*)d_in[13];
    float* out = (float*)d_out;

    float *melX, *mel, *q, *kv, *S, *ctx, *attn, *ga, *gb, *gX;
    int* rowsrc;
    cudaGetSymbolAddress((void**)&melX,   d_melX);
    cudaGetSymbolAddress((void**)&mel,    d_mel);
    cudaGetSymbolAddress((void**)&q,      d_q);
    cudaGetSymbolAddress((void**)&kv,     d_kv);
    cudaGetSymbolAddress((void**)&S,      d_S);
    cudaGetSymbolAddress((void**)&ctx,    d_ctx);
    cudaGetSymbolAddress((void**)&attn,   d_attn);
    cudaGetSymbolAddress((void**)&ga,     d_ga);
    cudaGetSymbolAddress((void**)&gb,     d_gb);
    cudaGetSymbolAddress((void**)&gX,     d_gX);
    cudaGetSymbolAddress((void**)&rowsrc, d_rowsrc);

    // 1) mel conv as GEMM: mel[8192,512] = im2col(mel_spec)[8192,240] @ mel_w[512,240]^T + b
    im2col_mel<<<2560, 256>>>(mel_spec, melX);
    gemm_kernel<true, false><<<dim3(8, 64, 1), 256>>>(
        8192, 512, 240, melX, 240, 0, 0, mel_w, 240, 0, 0,
        mel, 512, 0, 0, mel_b, 1.f, 1);

    // 2) q = phone @ Wq^T + bq
    gemm_kernel<true, false><<<dim3(8, 16, 1), 256>>>(
        2048, 512, 512, phone, 512, 0, 0, inw, 512, 0, 0,
        q, 512, 0, 0, inb, 1.f, 1);

    // 3) kv = mel @ [Wk;Wv]^T + [bk;bv]
    gemm_kernel<true, false><<<dim3(16, 64, 1), 256>>>(
        8192, 1024, 512, mel, 512, 0, 0, inw + 512 * 512, 512, 0, 0,
        kv, 1024, 0, 0, inb + 512, 1.f, 1);

    // 4) S[z=b*8+h] = 0.125 * Q_h @ K_h^T   (z: b-stride / h-stride split)
    gemm_kernel<true, false><<<dim3(16, 2, 64), 256>>>(
        256, 1024, 64,
        q,  512, 131072, 64,
        kv, 1024, 1048576, 64,
        S,  1024, 2097152, 262144,
        nullptr, 0.125f, 8);

    // 5) row softmax (64*256 rows of 1024)
    softmax1024<<<16384, 256>>>(S);

    // 6) ctx_h = attn @ V_h  (B non-transposed: V is [K=1024 rows, N=64])
    gemm_kernel<false, false><<<dim3(1, 2, 64), 256>>>(
        256, 64, 1024,
        S,        1024, 2097152, 262144,
        kv + 512, 1024, 1048576, 64,
        ctx,      512,  131072,  64,
        nullptr, 1.f, 8);

    // 7) attn_out = ctx @ Wo^T + bo
    gemm_kernel<true, false><<<dim3(8, 16, 1), 256>>>(
        2048, 512, 512, ctx, 512, 0, 0, ow, 512, 0, 0,
        attn, 512, 0, 0, ob, 1.f, 1);

    // 8) g0 = relu(conv(gms)) as GEMM, K = 80*31 = 2480
    im2col_g0<<<640, 256>>>(gms, gX);
    gemm_kernel<true, true><<<dim3(8, 16, 1), 256>>>(
        2048, 512, 2480, gX, 2480, 0, 0, g0w, 2480, 0, 0,
        ga, 512, 0, 0, g0b, 1.f, 1);

    // 9) 4x g layers, K = 512*31 = 15872 (dominant cost)
    float* gin  = ga;
    float* gout = gb;
    for (int i = 0; i < 4; i++) {
        im2col_g<<<4096, 256>>>(gin, gX);
        gemm_kernel<true, true><<<dim3(8, 16, 1), 256>>>(
            2048, 512, 15872, gX, 15872, 0, 0,
            gws + (long long)i * 512 * 15872, 15872, 0, 0,
            gout, 512, 0, 0, gbs + i * 512, 1.f, 1);
        float* tmp = gin; gin = gout; gout = tmp;
    }
    // final g result is in `gin` (== ga after 4 swaps)

    // 10) length regulator: map + gather
    build_map<<<B_, LC_>>>(tl, rowsrc);
    gather_out<<<B_ * TOUT, 128>>>(rowsrc, attn, gin, out);
}

// round 7
// speedup vs baseline: 1.7887x; 1.7887x over previous
#include <cuda_runtime.h>
#include <cuda_bf16.h>
#include <math.h>
#include <stdint.h>

#define B_    8
#define LP    256
#define H_    512
#define LC_   512
#define TOUT  1536

__device__ __forceinline__ uint32_t s2u(const void* p){
    uint32_t a;
    asm("{ .reg .u64 t; cvta.to.shared.u64 t, %1; cvt.u32.u64 %0, t; }" : "=r"(a) : "l"(p));
    return a;
}

// ============================ device scratch ============================
__device__ float d_mel [8192 * 512];
__device__ float d_q   [2048 * 512];
__device__ float d_kv  [8192 * 1024];
__device__ float d_S   [64 * 256 * 1024];
__device__ float d_ctx [2048 * 512];
__device__ float d_attn[2048 * 512];
__device__ float d_ga  [2048 * 512];
__device__ float d_gb  [2048 * 512];
__device__ int   d_rowsrc[B_ * TOUT];

// bf16 hi/lo panels, plain row-major [Mpad][Kpad]; hi at 0, lo at +Mpad*Kpad
__device__ __nv_bfloat16 pAmel[2*8192*256];
__device__ __nv_bfloat16 pWmel[2*512*256];
__device__ __nv_bfloat16 pAph [2*2048*512];
__device__ __nv_bfloat16 pWq  [2*512*512];
__device__ __nv_bfloat16 pWkv [2*1024*512];
__device__ __nv_bfloat16 pWo  [2*512*512];
__device__ __nv_bfloat16 pAmf [2*8192*512];
__device__ __nv_bfloat16 pAcx [2*2048*512];
__device__ __nv_bfloat16 pAg0 [2*2048*2496];
__device__ __nv_bfloat16 pWg0 [2*512*2496];
__device__ __nv_bfloat16 pAct [2*2304*512];        // padded activations [8][288][512]
__device__ __nv_bfloat16 pWg  [4ll*2*512*15872];

// ============================ converter ============================
// modes: 0 row-major [m][p1]; 1 g-weight reorder k=kk*512+ci from [m][ci][kk];
// 2 mel-A im2col k=mc*3+kkk; 3 g0-A im2col k=mc*31+kk; 4 act-pad [b*288+rr][ci]
__device__ __forceinline__ float fetchv(const float* __restrict__ s, int m, int k,
                                        int mode, int p1)
{
    switch (mode) {
    case 0: return s[(long long)m * p1 + k];
    case 1: { int kk = k >> 9, ci = k & 511;
              return s[((long long)m * 512 + ci) * 31 + kk]; }
    case 2: { int mc = k / 3, kkk = k - mc * 3;
              int b = m >> 10, t = m & 1023, tt = t + kkk - 1;
              return (tt >= 0 && tt < 1024) ? s[(long long)(b * 80 + mc) * 1024 + tt] : 0.f; }
    case 3: { int mc = k / 31, kk = k - mc * 31;
              int b = m >> 8, t = m & 255, tt = t + kk - 15;
              return (tt >= 0 && tt < 256) ? s[(long long)(b * 80 + mc) * 256 + tt] : 0.f; }
    case 4: { int b = m / 288, rr = m - b * 288, t = rr - 16;
              return (t >= 0 && t < 256) ? s[(long long)(b * 256 + t) * 512 + k] : 0.f; }
    }
    return 0.f;
}

__global__ void to_bf(const float* __restrict__ src, int Mpad, int K, int Kpad,
                      int mode, int p1,
                      __nv_bfloat16* __restrict__ Ph, __nv_bfloat16* __restrict__ Pl,
                      long long total)
{
    long long idx = (long long)blockIdx.x * 256 + threadIdx.x;
    if (idx >= total) return;
    int kchunks = Kpad >> 3;
    int m  = (int)(idx / kchunks);
    int k0 = (int)(idx - (long long)m * kchunks) * 8;
    unsigned short h[8], l[8];
    #pragma unroll
    for (int j = 0; j < 8; j++) {
        int k = k0 + j;
        float v = (k < K) ? fetchv(src, m, k, mode, p1) : 0.f;
        __nv_bfloat16 hb = __float2bfloat16(v);
        __nv_bfloat16 lb = __float2bfloat16(v - __bfloat162float(hb));
        h[j] = *(unsigned short*)&hb;
        l[j] = *(unsigned short*)&lb;
    }
    long long off = (long long)m * Kpad + k0;
    *(uint4*)(Ph + off) = *(uint4*)h;
    *(uint4*)(Pl + off) = *(uint4*)l;
}

// ============================ mma.sync GEMM ============================
// C[M,N] = AhiBhi^T + AhiBlo^T + AloBhi^T (+bias)(+relu). BM=128 BN=64 BK=32, 3 stages.
// mode 0: A rows = [Mpad][Kpad]. mode 1 (conv): A = padded act [8][288][512],
//   k = kk*512+ci, tile rows are shifted activation rows.
#define STAGEB 15360            // A 128*80 + B 64*80
#define MMA16816(d, a, b0, b1) \
    asm volatile("mma.sync.aligned.m16n8k16.row.col.f32.bf16.bf16.f32 " \
        "{%0,%1,%2,%3},{%4,%5,%6,%7},{%8,%9},{%0,%1,%2,%3};" \
        : "+f"((d)[0]),"+f"((d)[1]),"+f"((d)[2]),"+f"((d)[3]) \
        : "r"((a)[0]),"r"((a)[1]),"r"((a)[2]),"r"((a)[3]),"r"(b0),"r"(b1))

__global__ void __launch_bounds__(256, 2)
gemm_mma(const __nv_bfloat16* __restrict__ Ah, const __nv_bfloat16* __restrict__ Al,
         const __nv_bfloat16* __restrict__ Bh, const __nv_bfloat16* __restrict__ Bl,
         float* __restrict__ C, int ldc, const float* __restrict__ bias,
         int relu, int mode, int Kpad, int KT1)
{
    __shared__ __align__(16) char smem[3 * STAGEB];
    const int tid = threadIdx.x, lane = tid & 31, warp = tid >> 5;
    const int m0 = blockIdx.y << 7, n0 = blockIdx.x << 6;
    const int KT3 = 3 * KT1;
    const size_t ldb = (size_t)Kpad * 2;
    uint32_t sbase = s2u(smem);

    auto issue = [&](int s, int ki) {
        if (ki < KT3) {
            int p  = (ki >= 2 * KT1) ? 2 : (ki >= KT1 ? 1 : 0);
            int k0 = (ki - p * KT1) * 32;
            const char* Ap = (const char*)((p == 2) ? Al : Ah);
            const char* Bp = (const char*)((p == 1) ? Bl : Bh);
            const char* ab; size_t astr;
            if (mode == 0) { ab = Ap + (size_t)m0 * ldb + k0 * 2; astr = ldb; }
            else { int kk = k0 >> 9, ci0 = k0 & 511;
                   int brow = (m0 >> 8) * 288 + 1 + (m0 & 255);
                   ab = Ap + (size_t)(brow + kk) * 1024 + ci0 * 2; astr = 1024; }
            const char* bb = Bp + (size_t)n0 * ldb + k0 * 2;
            uint32_t st = sbase + s * STAGEB;
            #pragma unroll
            for (int j = 0; j < 2; j++) {
                int idx = tid + j * 256, r = idx >> 2, c = idx & 3;
                uint32_t dst = st + r * 80 + c * 16;
                asm volatile("cp.async.cg.shared.global [%0], [%1], 16;"
                    :: "r"(dst), "l"(ab + (size_t)r * astr + c * 16) : "memory");
            }
            { int r = tid >> 2, c = tid & 3;
              uint32_t dst = st + 10240 + r * 80 + c * 16;
              asm volatile("cp.async.cg.shared.global [%0], [%1], 16;"
                  :: "r"(dst), "l"(bb + (size_t)r * ldb + c * 16) : "memory"); }
        }
        asm volatile("cp.async.commit_group;" ::: "memory");
    };

    float acc[2][4][4] = {};
    issue(0, 0); issue(1, 1);

    const int m_off = (warp >> 1) * 32, n_off = (warp & 1) * 32;
    const int arow = (lane & 15), acol = (lane >> 4) * 16;
    const int brow = ((lane >> 4) & 1) * 8 + (lane & 7), bcol = ((lane >> 3) & 1) * 16;

    for (int ki = 0; ki < KT3; ki++) {
        int s = ki % 3;
        asm volatile("cp.async.wait_group 1;" ::: "memory");
        __syncthreads();
        issue((ki + 2) % 3, ki + 2);

        uint32_t aT = sbase + s * STAGEB, bT = aT + 10240;
        #pragma unroll
        for (int h = 0; h < 2; h++) {
            uint32_t a[2][4], b[2][4];
            #pragma unroll
            for (int mt = 0; mt < 2; mt++) {
                uint32_t ad = aT + (m_off + mt * 16 + arow) * 80 + h * 32 + acol;
                asm volatile("ldmatrix.sync.aligned.m8n8.x4.shared.b16 {%0,%1,%2,%3},[%4];"
                    : "=r"(a[mt][0]),"=r"(a[mt][1]),"=r"(a[mt][2]),"=r"(a[mt][3]) : "r"(ad));
            }
            #pragma unroll
            for (int ng = 0; ng < 2; ng++) {
                uint32_t bd = bT + (n_off + ng * 16 + brow) * 80 + h * 32 + bcol;
                asm volatile("ldmatrix.sync.aligned.m8n8.x4.shared.b16 {%0,%1,%2,%3},[%4];"
                    : "=r"(b[ng][0]),"=r"(b[ng][1]),"=r"(b[ng][2]),"=r"(b[ng][3]) : "r"(bd));
            }
            #pragma unroll
            for (int mt = 0; mt < 2; mt++)
                #pragma unroll
                for (int nj = 0; nj < 4; nj++)
                    MMA16816(acc[mt][nj], a[mt], b[nj >> 1][(nj & 1) * 2], b[nj >> 1][(nj & 1) * 2 + 1]);
        }
    }

    // epilogue
    #pragma unroll
    for (int mt = 0; mt < 2; mt++)
        #pragma unroll
        for (int nj = 0; nj < 4; nj++) {
            int row = m0 + m_off + mt * 16 + (lane >> 2);
            int col = n0 + n_off + nj * 8 + (lane & 3) * 2;
            float b0 = bias ? bias[col] : 0.f, b1 = bias ? bias[col + 1] : 0.f;
            float2 v0 = { acc[mt][nj][0] + b0, acc[mt][nj][1] + b1 };
            float2 v1 = { acc[mt][nj][2] + b0, acc[mt][nj][3] + b1 };
            if (relu) {
                v0.x = fmaxf(v0.x, 0.f); v0.y = fmaxf(v0.y, 0.f);
                v1.x = fmaxf(v1.x, 0.f); v1.y = fmaxf(v1.y, 0.f);
            }
            *(float2*)(C + (long long)row * ldc + col) = v0;
            *(float2*)(C + (long long)(row + 8) * ldc + col) = v1;
        }
}

// ============================ SIMT GEMM (attention inner) ============================
template<bool TRANSB>
__global__ void __launch_bounds__(256, 2)
gemm_kernel(int M, int N, int K,
            const float* __restrict__ A, int lda, long long sA1, long long sA2,
            const float* __restrict__ Bp, int ldb, long long sB1, long long sB2,
            float* __restrict__ C, int ldc, long long sC1, long long sC2,
            float alpha, int zdiv)
{
    __shared__ float As[16][132];
    __shared__ float Bs[16][68];
    int z = blockIdx.z, z1 = z / zdiv, z2 = z - z1 * zdiv;
    A  += (long long)z1 * sA1 + (long long)z2 * sA2;
    Bp += (long long)z1 * sB1 + (long long)z2 * sB2;
    C  += (long long)z1 * sC1 + (long long)z2 * sC2;
    int tid = threadIdx.x, row0 = blockIdx.y * 128, col0 = blockIdx.x * 64;
    int am = tid >> 2, ak = (tid & 3) << 2, bn = tid >> 2, bk = (tid & 3) << 2;
    int bks = tid >> 4, bn4 = (tid & 15) << 2;
    const float* Arow0 = A + (long long)(row0 + am) * lda + ak;
    const float* Arow1 = Arow0 + (long long)64 * lda;
    const float* Brow  = TRANSB ? (Bp + (long long)(col0 + bn) * ldb + bk)
                                : (Bp + (long long)bks * ldb + col0 + bn4);
    float4 pa0 = *(const float4*)(Arow0);
    float4 pa1 = *(const float4*)(Arow1);
    float4 pb  = *(const float4*)(Brow);
    float acc[8][4];
    #pragma unroll
    for (int i = 0; i < 8; i++)
        #pragma unroll
        for (int j = 0; j < 4; j++) acc[i][j] = 0.f;
    int tm = (tid >> 4) << 3, tn = (tid & 15) << 2;
    for (int k0 = 0; k0 < K; k0 += 16) {
        As[ak+0][am]    = pa0.x; As[ak+1][am]    = pa0.y; As[ak+2][am]    = pa0.z; As[ak+3][am]    = pa0.w;
        As[ak+0][am+64] = pa1.x; As[ak+1][am+64] = pa1.y; As[ak+2][am+64] = pa1.z; As[ak+3][am+64] = pa1.w;
        if (TRANSB) { Bs[bk+0][bn] = pb.x; Bs[bk+1][bn] = pb.y; Bs[bk+2][bn] = pb.z; Bs[bk+3][bn] = pb.w; }
        else        { *(float4*)&Bs[bks][bn4] = pb; }
        __syncthreads();
        int kn = k0 + 16;
        if (kn < K) {
            pa0 = *(const float4*)(Arow0 + kn);
            pa1 = *(const float4*)(Arow1 + kn);
            pb  = TRANSB ? *(const float4*)(Brow + kn) : *(const float4*)(Brow + (long long)kn * ldb);
        }
        #pragma unroll
        for (int kk = 0; kk < 16; kk++) {
            float a[8], bb[4];
            *(float4*)&a[0]  = *(const float4*)&As[kk][tm];
            *(float4*)&a[4]  = *(const float4*)&As[kk][tm + 4];
            *(float4*)&bb[0] = *(const float4*)&Bs[kk][tn];
            #pragma unroll
            for (int i = 0; i < 8; i++)
                #pragma unroll
                for (int j = 0; j < 4; j++)
                    acc[i][j] = fmaf(a[i], bb[j], acc[i][j]);
        }
        __syncthreads();
    }
    #pragma unroll
    for (int i = 0; i < 8; i++) {
        float4 o;
        o.x = acc[i][0]*alpha; o.y = acc[i][1]*alpha; o.z = acc[i][2]*alpha; o.w = acc[i][3]*alpha;
        *(float4*)(C + (long long)(row0 + tm + i) * ldc + col0 + tn) = o;
    }
}

__global__ void softmax1024(float* __restrict__ S)
{
    float4* row = (float4*)(S + (long long)blockIdx.x * 1024);
    int tid = threadIdx.x;
    float4 v = row[tid];
    float m = fmaxf(fmaxf(v.x, v.y), fmaxf(v.z, v.w));
    __shared__ float red[8];
    #pragma unroll
    for (int o = 16; o; o >>= 1) m = fmaxf(m, __shfl_xor_sync(0xffffffffu, m, o));
    if ((tid & 31) == 0) red[tid >> 5] = m;
    __syncthreads();
    float bm = red[0];
    #pragma unroll
    for (int i = 1; i < 8; i++) bm = fmaxf(bm, red[i]);
    v.x = expf(v.x - bm); v.y = expf(v.y - bm); v.z = expf(v.z - bm); v.w = expf(v.w - bm);
    float s = v.x + v.y + v.z + v.w;
    #pragma unroll
    for (int o = 16; o; o >>= 1) s += __shfl_xor_sync(0xffffffffu, s, o);
    __syncthreads();
    if ((tid & 31) == 0) red[tid >> 5] = s;
    __syncthreads();
    float bs = 0.f;
    #pragma unroll
    for (int i = 0; i < 8; i++) bs += red[i];
    float inv = 1.f / bs;
    v.x *= inv; v.y *= inv; v.z *= inv; v.w *= inv;
    row[tid] = v;
}

__global__ void build_map(const int* __restrict__ tl, int* __restrict__ rowsrc)
{
    int b = blockIdx.x;
    __shared__ int cum[LC_];
    int l = threadIdx.x;
    cum[l] = tl[b * LC_ + l];
    __syncthreads();
    if (l == 0) { int s = 0; for (int i = 0; i < LC_; i++) { s += cum[i]; cum[i] = s; } }
    __syncthreads();
    for (int t = l; t < TOUT; t += LC_) rowsrc[b * TOUT + t] = -1;
    __syncthreads();
    int e = cum[l], s = e - tl[b * LC_ + l];
    for (int t = s; t < e; t++) rowsrc[b * TOUT + t] = l;
}

__global__ void gather_out(const int* __restrict__ rowsrc, const float* __restrict__ attn,
                           const float* __restrict__ g, float* __restrict__ out)
{
    int bt = blockIdx.x, b = bt / TOUT, l = rowsrc[bt];
    float4 v = make_float4(0.f, 0.f, 0.f, 0.f);
    if (l >= 0) {
        const float* src = (l < LP) ? attn + (long long)(b * LP + l) * H_
                                    : g    + (long long)(b * 256 + (l - LP)) * H_;
        v = ((const float4*)src)[threadIdx.x];
    }
    ((float4*)(out + (long long)bt * H_))[threadIdx.x] = v;
}

// ============================ launch ============================
static void TB(const float* src, int Mpad, int K, int Kpad, int mode, int p1,
               __nv_bfloat16* P)
{
    long long total = (long long)Mpad * (Kpad >> 3);
    to_bf<<<(unsigned)((total + 255) / 256), 256>>>(src, Mpad, K, Kpad, mode, p1,
        P, P + (long long)Mpad * Kpad, total);
}
static void GM(__nv_bfloat16* A, long long aElems, __nv_bfloat16* Bw, long long bElems,
               float* C, int ldc, const float* bias, int relu, int mode,
               int Kpad, int M, int N)
{
    gemm_mma<<<dim3(N / 64, M / 128), 256>>>(A, A + aElems, Bw, Bw + bElems,
        C, ldc, bias, relu, mode, Kpad, Kpad / 32);
}

extern "C" void kernel_launch(void* const* d_in, const int* in_sizes, int n_in,
                              void* d_out, int out_size)
{
    const float* phone    = (const float*)d_in[0];
    const float* mel_spec = (const float*)d_in[1];
    const float* gms      = (const float*)d_in[2];
    const int*   tl       = (const int*)  d_in[3];
    const float* mel_w    = (const float*)d_in[4];
    const float* mel_b    = (const float*)d_in[5];
    const float* inw      = (const float*)d_in[6];
    const float* inb      = (const float*)d_in[7];
    const float* ow       = (const float*)d_in[8];
    const float* ob       = (const float*)d_in[9];
    const float* g0w      = (const float*)d_in[10];
    const float* g0b      = (const float*)d_in[11];
    const float* gws      = (const float*)d_in[12];
    const float* gbs      = (const float*)d_in[13];
    float* out = (float*)d_out;

    #define SYM(T, v, s) T* v; cudaGetSymbolAddress((void**)&v, s)
    SYM(float, mel, d_mel); SYM(float, q, d_q); SYM(float, kv, d_kv);
    SYM(float, S, d_S); SYM(float, ctx, d_ctx); SYM(float, attn, d_attn);
    SYM(float, ga, d_ga); SYM(float, gb, d_gb); SYM(int, rowsrc, d_rowsrc);
    SYM(__nv_bfloat16, amel, pAmel); SYM(__nv_bfloat16, wmel, pWmel);
    SYM(__nv_bfloat16, aph, pAph);   SYM(__nv_bfloat16, wq, pWq);
    SYM(__nv_bfloat16, wkvp, pWkv);  SYM(__nv_bfloat16, wo, pWo);
    SYM(__nv_bfloat16, amf, pAmf);   SYM(__nv_bfloat16, acx, pAcx);
    SYM(__nv_bfloat16, ag0, pAg0);   SYM(__nv_bfloat16, wg0, pWg0);
    SYM(__nv_bfloat16, act, pAct);   SYM(__nv_bfloat16, wg, pWg);

    // ---- convert static operands ----
    TB(mel_spec, 8192, 240, 256, 2, 0, amel);
    TB(mel_w,    512,  240, 256, 0, 240, wmel);
    TB(phone,    2048, 512, 512, 0, 512, aph);
    TB(inw,           512,  512, 512, 0, 512, wq);
    TB(inw + 512*512, 1024, 512, 512, 0, 512, wkvp);
    TB(ow,       512,  512, 512, 0, 512, wo);
    TB(gms,      2048, 2480, 2496, 3, 0, ag0);
    TB(g0w,      512,  2480, 2496, 0, 2480, wg0);
    long long wgE = 2ll * 512 * 15872;
    for (int i = 0; i < 4; i++)
        TB(gws + (long long)i * 512 * 512 * 31, 512, 15872, 15872, 1, 0, wg + i * wgE);

    // ---- mel conv ----
    GM(amel, 8192ll*256, wmel, 512ll*256, mel, 512, mel_b, 0, 0, 256, 8192, 512);
    // ---- q ----
    GM(aph, 2048ll*512, wq, 512ll*512, q, 512, inb, 0, 0, 512, 2048, 512);
    // ---- kv ----
    TB(mel, 8192, 512, 512, 0, 512, amf);
    GM(amf, 8192ll*512, wkvp, 1024ll*512, kv, 1024, inb + 512, 0, 0, 512, 8192, 1024);

    // ---- attention (SIMT fp32) ----
    gemm_kernel<true><<<dim3(16, 2, 64), 256>>>(256, 1024, 64,
        q, 512, 131072, 64, kv, 1024, 1048576, 64,
        S, 1024, 2097152, 262144, 0.125f, 8);
    softmax1024<<<16384, 256>>>(S);
    gemm_kernel<false><<<dim3(1, 2, 64), 256>>>(256, 64, 1024,
        S, 1024, 2097152, 262144, kv + 512, 1024, 1048576, 64,
        ctx, 512, 131072, 64, 1.f, 8);

    // ---- out proj ----
    TB(ctx, 2048, 512, 512, 0, 512, acx);
    GM(acx, 2048ll*512, wo, 512ll*512, attn, 512, ob, 0, 0, 512, 2048, 512);

    // ---- g0 ----
    GM(ag0, 2048ll*2496, wg0, 512ll*2496, ga, 512, g0b, 1, 0, 2496, 2048, 512);

    // ---- 4x g conv layers (conv-aware A addressing) ----
    float* gin = ga; float* gout = gb;
    for (int i = 0; i < 4; i++) {
        TB(gin, 2304, 512, 512, 4, 0, act);
        GM(act, 2304ll*512, wg + i * wgE, 512ll*15872,
           gout, 512, gbs + i * 512, 1, 1, 15872, 2048, 512);
        float* t = gin; gin = gout; gout = t;
    }

    // ---- length regulator ----
    build_map<<<B_, LC_>>>(tl, rowsrc);
    gather_out<<<B_ * TOUT, 128>>>(rowsrc, attn, gin, out);
}